// round 6
// baseline (speedup 1.0000x reference)
#include <cuda_runtime.h>
#include <cuda_bf16.h>
#include <cstdint>

#define NB 32
#define NN 1024
#define NF 32
#define ND 64
#define NH 64
#define NJ (NB*ND)   /* 2048 */

// ---------------- scratch (device globals; no allocations) ----------------
__device__ __align__(16) float g_MU1[NN*NJ];            // mu_1, layout [n][b*64+d]
__device__ __align__(16) float g_MUF[NN*NJ];            // current mu state fp32
__device__ __align__(16) __nv_bfloat16 g_Abin[NN*NN];   // binarized adjacency
__device__ __align__(16) __nv_bfloat16 g_Vhi[NN*NJ];    // V = mu @ W2^T, bf16 high part
__device__ __align__(16) __nv_bfloat16 g_Vlo[NN*NJ];    // bf16 residual (v - hi)
__device__ __align__(16) float g_C3[NN*ND];             // mu3[n,d] + b2[d]
__device__ __align__(16) float g_T2[NB*NH];             // option branch thru Wreg + breg
__device__ __align__(16) float g_MMEAN[NB*ND];          // relu(mean @ Wq1^T + bq1)

// ---------------- binarize adjacency ----------------
__global__ void k_binarize(const float* __restrict__ adj) {
    int i = blockIdx.x * blockDim.x + threadIdx.x;
    if (i < NN*NN) g_Abin[i] = __float2bfloat16(adj[i] > 0.f ? 1.f : 0.f);
}

// ---------------- mu_1 = relu(xv @ mu1), also init state ----------------
__global__ __launch_bounds__(256) void k_mu1(const float* __restrict__ xv,
                                             const float* __restrict__ mu1w) {
    __shared__ float xs[128][NF];
    int mt = blockIdx.x, b = blockIdx.y;
    int n0 = mt * 128, tid = threadIdx.x;
    #pragma unroll
    for (int i = 0; i < 4; ++i) {
        int q = tid + i*256;                  // 1024 float4 total
        int r = q >> 3, f4 = (q & 7) * 4;
        *(float4*)&xs[r][f4] = *(const float4*)&xv[(size_t)(b*NN + n0 + r)*NF + f4];
    }
    __syncthreads();
    int d = tid & 63, rq = tid >> 6;
    float w[NF];
    #pragma unroll
    for (int f = 0; f < NF; ++f) w[f] = mu1w[f*ND + d];
    for (int i = 0; i < 32; ++i) {
        int r = rq*32 + i;
        float acc = 0.f;
        #pragma unroll
        for (int f = 0; f < NF; ++f) acc = fmaf(xs[r][f], w[f], acc);
        acc = fmaxf(acc, 0.f);
        int o = (n0 + r)*NJ + b*ND + d;
        g_MU1[o] = acc;
        g_MUF[o] = acc;                       // t = 0 state
    }
}

// ---------------- C3 = mu3 + b2 (loop-invariant) ----------------
__global__ __launch_bounds__(64) void k_mu34(const float* __restrict__ adj,
        const float* __restrict__ W3, const float* __restrict__ b3,
        const float* __restrict__ W4, const float* __restrict__ b4,
        const float* __restrict__ b2) {
    __shared__ float adjs[NN];
    __shared__ float mu4s[ND];
    int n = blockIdx.x, tid = threadIdx.x;
    #pragma unroll
    for (int i = 0; i < 4; ++i) {
        int q = tid + i*64;
        *(float4*)&adjs[q*4] = *(const float4*)&adj[n*NN + q*4];
    }
    __syncthreads();
    float w4 = W4[tid], bb4 = b4[tid];
    float acc = 0.f;
    #pragma unroll 8
    for (int m = 0; m < NN; ++m) acc += fmaxf(fmaf(adjs[m], w4, bb4), 0.f);
    mu4s[tid] = acc;
    __syncthreads();
    float a2 = b3[tid] + b2[tid];
    #pragma unroll 8
    for (int dp = 0; dp < ND; ++dp) a2 = fmaf(mu4s[dp], W3[tid*ND + dp], a2);
    g_C3[n*ND + tid] = a2;
}

// ---------------- T2[b,h] = option branch through Wreg + breg ----------------
__global__ __launch_bounds__(64) void k_t2(const float* __restrict__ option,
        const float* __restrict__ Wq2, const float* __restrict__ bq2,
        const float* __restrict__ Wreg, const float* __restrict__ breg) {
    int b = blockIdx.x, h = threadIdx.x;
    float opt = option[b];
    float acc = breg[h];
    #pragma unroll 8
    for (int d = 0; d < ND; ++d)
        acc = fmaf(fmaf(opt, Wq2[d], bq2[d]), Wreg[h*(2*ND) + ND + d], acc);
    g_T2[b*NH + h] = acc;
}

// ---------------- V = MUF @ W2^T  (fp32 compute, split bf16 out) ----------------
__global__ __launch_bounds__(256) void k_proj(const float* __restrict__ W2) {
    __shared__ float mus[64][65];
    __shared__ float w2s[64][65];
    int mt = blockIdx.x, b = blockIdx.y;
    int m0 = mt * 64, tid = threadIdx.x;
    #pragma unroll
    for (int i = 0; i < 4; ++i) {
        int q = tid + i*256;                  // 1024 float4 each
        int r = q >> 4, dq = (q & 15) * 4;
        float4 v = *(const float4*)&g_MUF[(size_t)(m0 + r)*NJ + b*ND + dq];
        mus[r][dq] = v.x; mus[r][dq+1] = v.y; mus[r][dq+2] = v.z; mus[r][dq+3] = v.w;
        float4 w = *(const float4*)&W2[r*ND + dq];
        w2s[r][dq] = w.x; w2s[r][dq+1] = w.y; w2s[r][dq+2] = w.z; w2s[r][dq+3] = w.w;
    }
    __syncthreads();
    int tx = tid & 15, ty = tid >> 4;
    float acc[4][4] = {};
    for (int dp = 0; dp < ND; ++dp) {
        float mv[4], wv[4];
        #pragma unroll
        for (int j = 0; j < 4; ++j) mv[j] = mus[ty + 16*j][dp];
        #pragma unroll
        for (int j = 0; j < 4; ++j) wv[j] = w2s[tx + 16*j][dp];
        #pragma unroll
        for (int ii = 0; ii < 4; ++ii)
            #pragma unroll
            for (int jj = 0; jj < 4; ++jj) acc[ii][jj] = fmaf(mv[ii], wv[jj], acc[ii][jj]);
    }
    #pragma unroll
    for (int ii = 0; ii < 4; ++ii)
        #pragma unroll
        for (int jj = 0; jj < 4; ++jj) {
            int r = ty + 16*ii, d = tx + 16*jj;
            size_t o = (size_t)(m0 + r)*NJ + b*ND + d;
            float v = acc[ii][jj];
            __nv_bfloat16 hi = __float2bfloat16(v);
            g_Vhi[o] = hi;
            g_Vlo[o] = __float2bfloat16(v - __bfloat162float(hi));
        }
}

// ------- big GEMM: MUF_new = relu(A @ (Vhi + Vlo) + MU1 + C3), split-bf16 -------
#define BM 128
#define BJ 128
#define BK 32
#define PITCH 40
#define KT (NN / BK)

__global__ __launch_bounds__(256) void k_gemm() {
    __shared__ __align__(16) __nv_bfloat16 As[BM*PITCH];   // [m][k]
    __shared__ __align__(16) __nv_bfloat16 Bh[BJ*PITCH];   // [j][k] V_hi transposed
    __shared__ __align__(16) __nv_bfloat16 Bl[BJ*PITCH];   // [j][k] V_lo transposed
    int jt = blockIdx.x, mt = blockIdx.y;
    int m0 = mt * BM, j0 = jt * BJ;
    int tid = threadIdx.x, lane = tid & 31, warp = tid >> 5;
    int wm = warp >> 2, wj = warp & 3;      // 2 x 4 warps, warp tile 64m x 32j
    int g = lane >> 2, t = lane & 3;

    float acc[4][4][4];
    #pragma unroll
    for (int a = 0; a < 4; ++a)
        #pragma unroll
        for (int c = 0; c < 4; ++c)
            #pragma unroll
            for (int e = 0; e < 4; ++e) acc[a][c][e] = 0.f;

    // prologue: tile 0 -> smem
    #pragma unroll
    for (int i = 0; i < 2; ++i) {
        int idx = tid + i*256;
        int row = idx >> 2, kq = idx & 3;
        *(uint4*)&As[row*PITCH + kq*8] =
            *(const uint4*)&g_Abin[(size_t)(m0 + row)*NN + kq*8];
        int joct = idx & 15, krow = idx >> 4;
        union { uint4 u; __nv_bfloat16 h[8]; } vh, vl;
        vh.u = *(const uint4*)&g_Vhi[(size_t)krow*NJ + j0 + joct*8];
        vl.u = *(const uint4*)&g_Vlo[(size_t)krow*NJ + j0 + joct*8];
        #pragma unroll
        for (int e = 0; e < 8; ++e) {
            Bh[(joct*8 + e)*PITCH + krow] = vh.h[e];
            Bl[(joct*8 + e)*PITCH + krow] = vl.h[e];
        }
    }
    __syncthreads();

    for (int kt = 0; kt < KT; ++kt) {
        uint4 pa[2];
        union { uint4 u; __nv_bfloat16 h[8]; } pbh[2], pbl[2];
        bool next = (kt + 1 < KT);
        if (next) {
            int k0 = (kt + 1) * BK;
            #pragma unroll
            for (int i = 0; i < 2; ++i) {
                int idx = tid + i*256;
                int row = idx >> 2, kq = idx & 3;
                pa[i] = *(const uint4*)&g_Abin[(size_t)(m0 + row)*NN + k0 + kq*8];
                int joct = idx & 15, krow = idx >> 4;
                pbh[i].u = *(const uint4*)&g_Vhi[(size_t)(k0 + krow)*NJ + j0 + joct*8];
                pbl[i].u = *(const uint4*)&g_Vlo[(size_t)(k0 + krow)*NJ + j0 + joct*8];
            }
        }
        // compute on current smem tile
        #pragma unroll
        for (int ks = 0; ks < 2; ++ks) {
            int koff = ks * 16;
            uint32_t af[4][4], bfh[4][2], bfl[4][2];
            #pragma unroll
            for (int mf = 0; mf < 4; ++mf) {
                int rb = wm*64 + mf*16;
                af[mf][0] = *(const uint32_t*)&As[(rb+g  )*PITCH + koff + 2*t];
                af[mf][1] = *(const uint32_t*)&As[(rb+g+8)*PITCH + koff + 2*t];
                af[mf][2] = *(const uint32_t*)&As[(rb+g  )*PITCH + koff + 2*t + 8];
                af[mf][3] = *(const uint32_t*)&As[(rb+g+8)*PITCH + koff + 2*t + 8];
            }
            #pragma unroll
            for (int jf = 0; jf < 4; ++jf) {
                int jb = wj*32 + jf*8 + g;
                bfh[jf][0] = *(const uint32_t*)&Bh[jb*PITCH + koff + 2*t];
                bfh[jf][1] = *(const uint32_t*)&Bh[jb*PITCH + koff + 2*t + 8];
                bfl[jf][0] = *(const uint32_t*)&Bl[jb*PITCH + koff + 2*t];
                bfl[jf][1] = *(const uint32_t*)&Bl[jb*PITCH + koff + 2*t + 8];
            }
            #pragma unroll
            for (int mf = 0; mf < 4; ++mf)
                #pragma unroll
                for (int jf = 0; jf < 4; ++jf) {
                    asm volatile(
                        "mma.sync.aligned.m16n8k16.row.col.f32.bf16.bf16.f32 "
                        "{%0,%1,%2,%3}, {%4,%5,%6,%7}, {%8,%9}, {%0,%1,%2,%3};\n"
                        : "+f"(acc[mf][jf][0]), "+f"(acc[mf][jf][1]),
                          "+f"(acc[mf][jf][2]), "+f"(acc[mf][jf][3])
                        : "r"(af[mf][0]), "r"(af[mf][1]), "r"(af[mf][2]), "r"(af[mf][3]),
                          "r"(bfh[jf][0]), "r"(bfh[jf][1]));
                    asm volatile(
                        "mma.sync.aligned.m16n8k16.row.col.f32.bf16.bf16.f32 "
                        "{%0,%1,%2,%3}, {%4,%5,%6,%7}, {%8,%9}, {%0,%1,%2,%3};\n"
                        : "+f"(acc[mf][jf][0]), "+f"(acc[mf][jf][1]),
                          "+f"(acc[mf][jf][2]), "+f"(acc[mf][jf][3])
                        : "r"(af[mf][0]), "r"(af[mf][1]), "r"(af[mf][2]), "r"(af[mf][3]),
                          "r"(bfl[jf][0]), "r"(bfl[jf][1]));
                }
        }
        __syncthreads();          // done reading current tile
        if (next) {
            #pragma unroll
            for (int i = 0; i < 2; ++i) {
                int idx = tid + i*256;
                int row = idx >> 2, kq = idx & 3;
                *(uint4*)&As[row*PITCH + kq*8] = pa[i];
                int joct = idx & 15, krow = idx >> 4;
                #pragma unroll
                for (int e = 0; e < 8; ++e) {
                    Bh[(joct*8 + e)*PITCH + krow] = pbh[i].h[e];
                    Bl[(joct*8 + e)*PITCH + krow] = pbl[i].h[e];
                }
            }
        }
        __syncthreads();          // next tile visible to all warps
    }

    // epilogue: relu(acc + MU1 + C3) -> MUF
    #pragma unroll
    for (int mf = 0; mf < 4; ++mf)
        #pragma unroll
        for (int jf = 0; jf < 4; ++jf) {
            int n0r = m0 + wm*64 + mf*16 + g;
            int jc = j0 + wj*32 + jf*8 + 2*t;
            int dd = jc & 63;
            float2 m1 = *(const float2*)&g_MU1[(size_t)n0r*NJ + jc];
            float2 c3 = *(const float2*)&g_C3[n0r*ND + dd];
            float2 o0;
            o0.x = fmaxf(acc[mf][jf][0] + m1.x + c3.x, 0.f);
            o0.y = fmaxf(acc[mf][jf][1] + m1.y + c3.y, 0.f);
            *(float2*)&g_MUF[(size_t)n0r*NJ + jc] = o0;
            float2 m1b = *(const float2*)&g_MU1[(size_t)(n0r+8)*NJ + jc];
            float2 c3b = *(const float2*)&g_C3[(n0r+8)*ND + dd];
            float2 o1;
            o1.x = fmaxf(acc[mf][jf][2] + m1b.x + c3b.x, 0.f);
            o1.y = fmaxf(acc[mf][jf][3] + m1b.y + c3b.y, 0.f);
            *(float2*)&g_MUF[(size_t)(n0r+8)*NJ + jc] = o1;
        }
}

// ---------------- mean over nodes + Wq1 layer ----------------
__global__ __launch_bounds__(256) void k_mean(const float* __restrict__ Wq1,
                                              const float* __restrict__ bq1) {
    __shared__ float red[4][ND];
    __shared__ float means[ND];
    int b = blockIdx.x, tid = threadIdx.x;
    int d = tid & 63, no = tid >> 6;
    float s = 0.f;
    for (int n = no; n < NN; n += 4) s += g_MUF[(size_t)n*NJ + b*ND + d];
    red[no][d] = s;
    __syncthreads();
    if (tid < ND)
        means[tid] = (red[0][tid] + red[1][tid] + red[2][tid] + red[3][tid]) * (1.0f/NN);
    __syncthreads();
    if (tid < ND) {
        float acc = bq1[tid];
        #pragma unroll 8
        for (int dp = 0; dp < ND; ++dp) acc = fmaf(means[dp], Wq1[tid*ND + dp], acc);
        g_MMEAN[b*ND + tid] = fmaxf(acc, 0.f);
    }
}

// ---------------- head: out = relu(q_ @ Wreg^T + breg) @ Wq^T + bq ----------------
__global__ __launch_bounds__(256) void k_head(const float* __restrict__ Wreg,
        const float* __restrict__ Wq, const float* __restrict__ bq,
        float* __restrict__ out) {
    __shared__ float xs[64][ND];
    __shared__ float Ws[NH][ND + 1];
    __shared__ float wqs[NH];
    int rt = blockIdx.x, b = blockIdx.y;
    int r0 = rt * 64, tid = threadIdx.x, lane = tid & 31, warp = tid >> 5;
    #pragma unroll
    for (int i = 0; i < 4; ++i) {
        int q = tid + i*256;                  // 1024 float4
        int h = q >> 4, dq = (q & 15) * 4;
        float4 w = *(const float4*)&Wreg[h*(2*ND) + dq];
        Ws[h][dq] = w.x; Ws[h][dq+1] = w.y; Ws[h][dq+2] = w.z; Ws[h][dq+3] = w.w;
    }
    if (tid < NH) wqs[tid] = Wq[tid];
    #pragma unroll
    for (int i = 0; i < 4; ++i) {
        int q = tid + i*256;
        int r = q >> 4, dq = (q & 15) * 4;
        int rr = r0 + r;
        float4 v;
        if (rr < NN)       v = *(const float4*)&g_MUF[(size_t)rr*NJ + b*ND + dq];
        else if (rr == NN) v = *(const float4*)&g_MMEAN[b*ND + dq];
        else               v = make_float4(0.f, 0.f, 0.f, 0.f);
        *(float4*)&xs[r][dq] = v;
    }
    __syncthreads();
    float g0i = g_T2[b*NH + lane], g1i = g_T2[b*NH + lane + 32];
    float wq0 = wqs[lane], wq1 = wqs[lane + 32];
    for (int jj = 0; jj < 8; ++jj) {
        int r = warp*8 + jj;
        int rr = r0 + r;
        float a0 = g0i, a1 = g1i;
        #pragma unroll 16
        for (int dp = 0; dp < ND; ++dp) {
            float xd = xs[r][dp];
            a0 = fmaf(xd, Ws[lane][dp], a0);
            a1 = fmaf(xd, Ws[lane + 32][dp], a1);
        }
        float v = fmaxf(a0, 0.f)*wq0 + fmaxf(a1, 0.f)*wq1;
        #pragma unroll
        for (int o = 16; o; o >>= 1) v += __shfl_xor_sync(0xffffffffu, v, o);
        if (lane == 0 && rr <= NN) out[b*(NN + 1) + rr] = v + bq[0];
    }
}

// ---------------- launch ----------------
extern "C" void kernel_launch(void* const* d_in, const int* in_sizes, int n_in,
                              void* d_out, int out_size) {
    const float* xv     = (const float*)d_in[0];
    const float* option = (const float*)d_in[1];
    const float* adj    = (const float*)d_in[2];
    const float* mu1w   = (const float*)d_in[3];
    const float* W2     = (const float*)d_in[4];
    const float* b2     = (const float*)d_in[5];
    const float* W3     = (const float*)d_in[6];
    const float* b3     = (const float*)d_in[7];
    const float* W4     = (const float*)d_in[8];
    const float* b4     = (const float*)d_in[9];
    const float* Wq1    = (const float*)d_in[10];
    const float* bq1    = (const float*)d_in[11];
    const float* Wq2    = (const float*)d_in[12];
    const float* bq2    = (const float*)d_in[13];
    const float* Wreg   = (const float*)d_in[14];
    const float* breg   = (const float*)d_in[15];
    const float* Wq     = (const float*)d_in[16];
    const float* bq     = (const float*)d_in[17];
    float* out = (float*)d_out;

    k_binarize<<<NN*NN/256, 256>>>(adj);
    k_mu1<<<dim3(8, NB), 256>>>(xv, mu1w);
    k_mu34<<<NN, 64>>>(adj, W3, b3, W4, b4, b2);
    k_t2<<<NB, 64>>>(option, Wq2, bq2, Wreg, breg);
    for (int t = 1; t < 4; ++t) {
        k_proj<<<dim3(16, NB), 256>>>(W2);   // V = MUF @ W2^T (split bf16)
        k_gemm<<<dim3(16, 8), 256>>>();      // MUF = relu(A @ V + MU1 + C3)
    }
    k_mean<<<NB, 256>>>(Wq1, bq1);
    k_head<<<dim3(17, NB), 256>>>(Wreg, Wq, bq, out);
}

// round 8
// speedup vs baseline: 1.6491x; 1.6491x over previous
#include <cuda_runtime.h>
#include <cuda_bf16.h>
#include <cstdint>

#define NB 32
#define NN 1024
#define NF 32
#define ND 64
#define NH 64
#define NJ (NB*ND)   /* 2048 */

// ---------------- scratch (device globals; no allocations) ----------------
__device__ __align__(16) float g_MU1[NN*NJ];            // mu_1, layout [n][b*64+d]
__device__ __align__(16) float g_MUF[NN*NJ];            // current mu state fp32
__device__ __align__(16) __nv_bfloat16 g_Abin[NN*NN];   // binarized adjacency
__device__ __align__(16) __nv_bfloat16 g_Vht[NJ*NN];    // V^T high part  [j][n]
__device__ __align__(16) __nv_bfloat16 g_Vlt[NJ*NN];    // V^T residual   [j][n]
__device__ __align__(16) float g_C3[NN*ND];             // mu3[n,d] + b2[d]

// ---------- fused: binarize adj row + C3 = mu3 + b2 (one pass over adj) ----------
__global__ __launch_bounds__(64) void k_adj(const float* __restrict__ adj,
        const float* __restrict__ W3, const float* __restrict__ b3,
        const float* __restrict__ W4, const float* __restrict__ b4,
        const float* __restrict__ b2) {
    __shared__ float adjs[NN];
    __shared__ float mu4s[ND];
    int n = blockIdx.x, tid = threadIdx.x;
    #pragma unroll
    for (int i = 0; i < 4; ++i) {
        int q = tid + i*64;
        *(float4*)&adjs[q*4] = *(const float4*)&adj[(size_t)n*NN + q*4];
    }
    __syncthreads();
    // binarize this row -> g_Abin (uint4 = 8 bf16 per write)
    const __nv_bfloat16 one = __float2bfloat16(1.f);
    const __nv_bfloat16 zero = __float2bfloat16(0.f);
    #pragma unroll
    for (int i = 0; i < 2; ++i) {
        int idx = tid + i*64;                // 128 uint4 total
        int base = idx * 8;
        union { uint4 u; __nv_bfloat16 h[8]; } w;
        #pragma unroll
        for (int e = 0; e < 8; ++e) w.h[e] = (adjs[base + e] > 0.f) ? one : zero;
        *(uint4*)&g_Abin[(size_t)n*NN + base] = w.u;
    }
    // mu4 = sum_m relu(adj[n][m]*W4 + b4)
    float w4 = W4[tid], bb4 = b4[tid];
    float acc = 0.f;
    #pragma unroll 8
    for (int m = 0; m < NN; ++m) acc += fmaxf(fmaf(adjs[m], w4, bb4), 0.f);
    mu4s[tid] = acc;
    __syncthreads();
    float a2 = b3[tid] + b2[tid];
    #pragma unroll 8
    for (int dp = 0; dp < ND; ++dp) a2 = fmaf(mu4s[dp], W3[tid*ND + dp], a2);
    g_C3[n*ND + tid] = a2;
}

// ---------------- mu_1 = relu(xv @ mu1), also init state ----------------
__global__ __launch_bounds__(256) void k_mu1(const float* __restrict__ xv,
                                             const float* __restrict__ mu1w) {
    __shared__ float xs[128][NF];
    int mt = blockIdx.x, b = blockIdx.y;
    int n0 = mt * 128, tid = threadIdx.x;
    #pragma unroll
    for (int i = 0; i < 4; ++i) {
        int q = tid + i*256;                  // 1024 float4 total
        int r = q >> 3, f4 = (q & 7) * 4;
        *(float4*)&xs[r][f4] = *(const float4*)&xv[(size_t)(b*NN + n0 + r)*NF + f4];
    }
    __syncthreads();
    int d = tid & 63, rq = tid >> 6;
    float w[NF];
    #pragma unroll
    for (int f = 0; f < NF; ++f) w[f] = mu1w[f*ND + d];
    for (int i = 0; i < 32; ++i) {
        int r = rq*32 + i;
        float acc = 0.f;
        #pragma unroll
        for (int f = 0; f < NF; ++f) acc = fmaf(xs[r][f], w[f], acc);
        acc = fmaxf(acc, 0.f);
        int o = (n0 + r)*NJ + b*ND + d;
        g_MU1[o] = acc;
        g_MUF[o] = acc;                       // t = 0 state
    }
}

// ------- V = MUF @ W2^T (fp32), written TRANSPOSED split-bf16: g_Vt[j][n] -------
__global__ __launch_bounds__(256) void k_proj(const float* __restrict__ W2) {
    __shared__ __align__(16) char sbuf[2*64*65*4];      // 33.3 KB, reused
    float (*mus)[65] = (float(*)[65])sbuf;
    float (*w2s)[65] = (float(*)[65])(sbuf + 64*65*sizeof(float));
    int mt = blockIdx.x, b = blockIdx.y;
    int m0 = mt * 64, tid = threadIdx.x;
    #pragma unroll
    for (int i = 0; i < 4; ++i) {
        int q = tid + i*256;                  // 1024 float4 each
        int r = q >> 4, dq = (q & 15) * 4;
        float4 v = *(const float4*)&g_MUF[(size_t)(m0 + r)*NJ + b*ND + dq];
        mus[r][dq] = v.x; mus[r][dq+1] = v.y; mus[r][dq+2] = v.z; mus[r][dq+3] = v.w;
        float4 w = *(const float4*)&W2[r*ND + dq];
        w2s[r][dq] = w.x; w2s[r][dq+1] = w.y; w2s[r][dq+2] = w.z; w2s[r][dq+3] = w.w;
    }
    __syncthreads();
    int tx = tid & 15, ty = tid >> 4;
    float acc[4][4] = {};
    for (int dp = 0; dp < ND; ++dp) {
        float mv[4], wv[4];
        #pragma unroll
        for (int j = 0; j < 4; ++j) mv[j] = mus[ty + 16*j][dp];
        #pragma unroll
        for (int j = 0; j < 4; ++j) wv[j] = w2s[tx + 16*j][dp];
        #pragma unroll
        for (int ii = 0; ii < 4; ++ii)
            #pragma unroll
            for (int jj = 0; jj < 4; ++jj) acc[ii][jj] = fmaf(mv[ii], wv[jj], acc[ii][jj]);
    }
    __syncthreads();                          // done with mus/w2s; reuse sbuf
    __nv_bfloat16 (*vhi)[72] = (__nv_bfloat16(*)[72])sbuf;
    __nv_bfloat16 (*vlo)[72] = (__nv_bfloat16(*)[72])(sbuf + 64*72*sizeof(__nv_bfloat16));
    #pragma unroll
    for (int ii = 0; ii < 4; ++ii)
        #pragma unroll
        for (int jj = 0; jj < 4; ++jj) {
            int r = ty + 16*ii, d = tx + 16*jj;
            float v = acc[ii][jj];
            __nv_bfloat16 hi = __float2bfloat16(v);
            vhi[d][r] = hi;
            vlo[d][r] = __float2bfloat16(v - __bfloat162float(hi));
        }
    __syncthreads();
    #pragma unroll
    for (int i = 0; i < 2; ++i) {
        int idx = tid + i*256;                // 512 uint4 per buffer
        int jd = idx >> 3, q = idx & 7;
        size_t go = (size_t)(b*ND + jd)*NN + m0 + q*8;
        *(uint4*)&g_Vht[go] = *(uint4*)&vhi[jd][q*8];
        *(uint4*)&g_Vlt[go] = *(uint4*)&vlo[jd][q*8];
    }
}

// ------- big GEMM: MUF_new = relu(A @ (Vhi + Vlo) + MU1 + C3), split-bf16 -------
#define BM 128
#define BJ 128
#define BK 32
#define PITCH 40
#define KT (NN / BK)

__global__ __launch_bounds__(256) void k_gemm() {
    __shared__ __align__(16) __nv_bfloat16 As[BM*PITCH];   // [m][k]
    __shared__ __align__(16) __nv_bfloat16 Bh[BJ*PITCH];   // [j][k] V_hi
    __shared__ __align__(16) __nv_bfloat16 Bl[BJ*PITCH];   // [j][k] V_lo
    int jt = blockIdx.x, mt = blockIdx.y;
    int m0 = mt * BM, j0 = jt * BJ;
    int tid = threadIdx.x, lane = tid & 31, warp = tid >> 5;
    int wm = warp >> 2, wj = warp & 3;      // 2 x 4 warps, warp tile 64m x 32j
    int g = lane >> 2, t = lane & 3;

    float acc[4][4][4];
    #pragma unroll
    for (int a = 0; a < 4; ++a)
        #pragma unroll
        for (int c = 0; c < 4; ++c)
            #pragma unroll
            for (int e = 0; e < 4; ++e) acc[a][c][e] = 0.f;

    // prologue: tile 0 -> smem  (all rows 128, k-chunk of 32 = 4 uint4/row)
    #pragma unroll
    for (int i = 0; i < 2; ++i) {
        int idx = tid + i*256;
        int row = idx >> 2, kq = idx & 3;
        *(uint4*)&As[row*PITCH + kq*8] =
            *(const uint4*)&g_Abin[(size_t)(m0 + row)*NN + kq*8];
        *(uint4*)&Bh[row*PITCH + kq*8] =
            *(const uint4*)&g_Vht[(size_t)(j0 + row)*NN + kq*8];
        *(uint4*)&Bl[row*PITCH + kq*8] =
            *(const uint4*)&g_Vlt[(size_t)(j0 + row)*NN + kq*8];
    }
    __syncthreads();

    for (int kt = 0; kt < KT; ++kt) {
        uint4 pa[2], pbh[2], pbl[2];
        bool next = (kt + 1 < KT);
        if (next) {
            int k0 = (kt + 1) * BK;
            #pragma unroll
            for (int i = 0; i < 2; ++i) {
                int idx = tid + i*256;
                int row = idx >> 2, kq = idx & 3;
                pa[i]  = *(const uint4*)&g_Abin[(size_t)(m0 + row)*NN + k0 + kq*8];
                pbh[i] = *(const uint4*)&g_Vht[(size_t)(j0 + row)*NN + k0 + kq*8];
                pbl[i] = *(const uint4*)&g_Vlt[(size_t)(j0 + row)*NN + k0 + kq*8];
            }
        }
        // compute on current smem tile
        #pragma unroll
        for (int ks = 0; ks < 2; ++ks) {
            int koff = ks * 16;
            uint32_t af[4][4], bfh[4][2], bfl[4][2];
            #pragma unroll
            for (int mf = 0; mf < 4; ++mf) {
                int rb = wm*64 + mf*16;
                af[mf][0] = *(const uint32_t*)&As[(rb+g  )*PITCH + koff + 2*t];
                af[mf][1] = *(const uint32_t*)&As[(rb+g+8)*PITCH + koff + 2*t];
                af[mf][2] = *(const uint32_t*)&As[(rb+g  )*PITCH + koff + 2*t + 8];
                af[mf][3] = *(const uint32_t*)&As[(rb+g+8)*PITCH + koff + 2*t + 8];
            }
            #pragma unroll
            for (int jf = 0; jf < 4; ++jf) {
                int jb = wj*32 + jf*8 + g;
                bfh[jf][0] = *(const uint32_t*)&Bh[jb*PITCH + koff + 2*t];
                bfh[jf][1] = *(const uint32_t*)&Bh[jb*PITCH + koff + 2*t + 8];
                bfl[jf][0] = *(const uint32_t*)&Bl[jb*PITCH + koff + 2*t];
                bfl[jf][1] = *(const uint32_t*)&Bl[jb*PITCH + koff + 2*t + 8];
            }
            #pragma unroll
            for (int mf = 0; mf < 4; ++mf)
                #pragma unroll
                for (int jf = 0; jf < 4; ++jf) {
                    asm volatile(
                        "mma.sync.aligned.m16n8k16.row.col.f32.bf16.bf16.f32 "
                        "{%0,%1,%2,%3}, {%4,%5,%6,%7}, {%8,%9}, {%0,%1,%2,%3};\n"
                        : "+f"(acc[mf][jf][0]), "+f"(acc[mf][jf][1]),
                          "+f"(acc[mf][jf][2]), "+f"(acc[mf][jf][3])
                        : "r"(af[mf][0]), "r"(af[mf][1]), "r"(af[mf][2]), "r"(af[mf][3]),
                          "r"(bfh[jf][0]), "r"(bfh[jf][1]));
                    asm volatile(
                        "mma.sync.aligned.m16n8k16.row.col.f32.bf16.bf16.f32 "
                        "{%0,%1,%2,%3}, {%4,%5,%6,%7}, {%8,%9}, {%0,%1,%2,%3};\n"
                        : "+f"(acc[mf][jf][0]), "+f"(acc[mf][jf][1]),
                          "+f"(acc[mf][jf][2]), "+f"(acc[mf][jf][3])
                        : "r"(af[mf][0]), "r"(af[mf][1]), "r"(af[mf][2]), "r"(af[mf][3]),
                          "r"(bfl[jf][0]), "r"(bfl[jf][1]));
                }
        }
        __syncthreads();          // done reading current tile
        if (next) {
            #pragma unroll
            for (int i = 0; i < 2; ++i) {
                int idx = tid + i*256;
                int row = idx >> 2, kq = idx & 3;
                *(uint4*)&As[row*PITCH + kq*8] = pa[i];
                *(uint4*)&Bh[row*PITCH + kq*8] = pbh[i];
                *(uint4*)&Bl[row*PITCH + kq*8] = pbl[i];
            }
        }
        __syncthreads();          // next tile visible to all warps
    }

    // epilogue: relu(acc + MU1 + C3) -> MUF
    #pragma unroll
    for (int mf = 0; mf < 4; ++mf)
        #pragma unroll
        for (int jf = 0; jf < 4; ++jf) {
            int n0r = m0 + wm*64 + mf*16 + g;
            int jc = j0 + wj*32 + jf*8 + 2*t;
            int dd = jc & 63;
            float2 m1 = *(const float2*)&g_MU1[(size_t)n0r*NJ + jc];
            float2 c3 = *(const float2*)&g_C3[n0r*ND + dd];
            float2 o0;
            o0.x = fmaxf(acc[mf][jf][0] + m1.x + c3.x, 0.f);
            o0.y = fmaxf(acc[mf][jf][1] + m1.y + c3.y, 0.f);
            *(float2*)&g_MUF[(size_t)n0r*NJ + jc] = o0;
            float2 m1b = *(const float2*)&g_MU1[(size_t)(n0r+8)*NJ + jc];
            float2 c3b = *(const float2*)&g_C3[(n0r+8)*ND + dd];
            float2 o1;
            o1.x = fmaxf(acc[mf][jf][2] + m1b.x + c3b.x, 0.f);
            o1.y = fmaxf(acc[mf][jf][3] + m1b.y + c3b.y, 0.f);
            *(float2*)&g_MUF[(size_t)(n0r+8)*NJ + jc] = o1;
        }
}

// ---- head (fused mean + option-branch): out = relu(q_@Wreg^T+breg)@Wq^T+bq ----
__global__ __launch_bounds__(256) void k_head(const float* __restrict__ Wreg,
        const float* __restrict__ Wq, const float* __restrict__ bq,
        const float* __restrict__ Wq1, const float* __restrict__ bq1,
        const float* __restrict__ option, const float* __restrict__ Wq2,
        const float* __restrict__ bq2, const float* __restrict__ breg,
        float* __restrict__ out) {
    __shared__ float xs[64][ND];
    __shared__ float Ws[NH][ND + 1];
    __shared__ float wqs[NH];
    __shared__ float t2s[NH];
    __shared__ float red[4][ND];
    __shared__ float means[ND];
    int rt = blockIdx.x, b = blockIdx.y;
    int r0 = rt * 64, tid = threadIdx.x, lane = tid & 31, warp = tid >> 5;
    // stage Wreg first half (mu part)
    #pragma unroll
    for (int i = 0; i < 4; ++i) {
        int q = tid + i*256;                  // 1024 float4
        int h = q >> 4, dq = (q & 15) * 4;
        float4 w = *(const float4*)&Wreg[h*(2*ND) + dq];
        Ws[h][dq] = w.x; Ws[h][dq+1] = w.y; Ws[h][dq+2] = w.z; Ws[h][dq+3] = w.w;
    }
    if (tid < NH) wqs[tid] = Wq[tid];
    // option branch: t2s[h] = breg[h] + sum_d (opt*Wq2[d]+bq2[d]) * Wreg[h][64+d]
    if (tid < NH) {
        float opt = option[b];
        float acc = breg[tid];
        #pragma unroll 8
        for (int d = 0; d < ND; ++d)
            acc = fmaf(fmaf(opt, Wq2[d], bq2[d]), Wreg[tid*(2*ND) + ND + d], acc);
        t2s[tid] = acc;
    }
    if (rt < 16) {
        // regular node rows
        #pragma unroll
        for (int i = 0; i < 4; ++i) {
            int q = tid + i*256;
            int r = q >> 4, dq = (q & 15) * 4;
            *(float4*)&xs[r][dq] = *(const float4*)&g_MUF[(size_t)(r0 + r)*NJ + b*ND + dq];
        }
    } else {
        // mean row: reduce MUF over nodes, project thru Wq1
        int d = tid & 63, no = tid >> 6;
        float s = 0.f;
        #pragma unroll 4
        for (int n = no; n < NN; n += 4) s += g_MUF[(size_t)n*NJ + b*ND + d];
        red[no][d] = s;
        __syncthreads();
        if (tid < ND)
            means[tid] = (red[0][tid] + red[1][tid] + red[2][tid] + red[3][tid]) * (1.0f/NN);
        __syncthreads();
        if (tid < ND) {
            float acc = bq1[tid];
            #pragma unroll 8
            for (int dp = 0; dp < ND; ++dp) acc = fmaf(means[dp], Wq1[tid*ND + dp], acc);
            xs[0][tid] = fmaxf(acc, 0.f);
        }
        // rows 1..63 unused (stores guarded below)
    }
    __syncthreads();
    float g0i = t2s[lane], g1i = t2s[lane + 32];
    float wq0 = wqs[lane], wq1 = wqs[lane + 32];
    for (int jj = 0; jj < 8; ++jj) {
        int r = warp*8 + jj;
        int rr = r0 + r;
        float a0 = g0i, a1 = g1i;
        #pragma unroll 16
        for (int dp = 0; dp < ND; ++dp) {
            float xd = xs[r][dp];
            a0 = fmaf(xd, Ws[lane][dp], a0);
            a1 = fmaf(xd, Ws[lane + 32][dp], a1);
        }
        float v = fmaxf(a0, 0.f)*wq0 + fmaxf(a1, 0.f)*wq1;
        #pragma unroll
        for (int o = 16; o; o >>= 1) v += __shfl_xor_sync(0xffffffffu, v, o);
        if (lane == 0 && rr <= NN) out[b*(NN + 1) + rr] = v + bq[0];
    }
}

// ---------------- launch ----------------
extern "C" void kernel_launch(void* const* d_in, const int* in_sizes, int n_in,
                              void* d_out, int out_size) {
    const float* xv     = (const float*)d_in[0];
    const float* option = (const float*)d_in[1];
    const float* adj    = (const float*)d_in[2];
    const float* mu1w   = (const float*)d_in[3];
    const float* W2     = (const float*)d_in[4];
    const float* b2     = (const float*)d_in[5];
    const float* W3     = (const float*)d_in[6];
    const float* b3     = (const float*)d_in[7];
    const float* W4     = (const float*)d_in[8];
    const float* b4     = (const float*)d_in[9];
    const float* Wq1    = (const float*)d_in[10];
    const float* bq1    = (const float*)d_in[11];
    const float* Wq2    = (const float*)d_in[12];
    const float* bq2    = (const float*)d_in[13];
    const float* Wreg   = (const float*)d_in[14];
    const float* breg   = (const float*)d_in[15];
    const float* Wq     = (const float*)d_in[16];
    const float* bq     = (const float*)d_in[17];
    float* out = (float*)d_out;

    k_adj<<<NN, 64>>>(adj, W3, b3, W4, b4, b2);          // binarize + C3
    k_mu1<<<dim3(8, NB), 256>>>(xv, mu1w);
    for (int t = 1; t < 4; ++t) {
        k_proj<<<dim3(16, NB), 256>>>(W2);   // V = MUF @ W2^T (split bf16, transposed)
        k_gemm<<<dim3(16, 8), 256>>>();      // MUF = relu(A @ V + MU1 + C3)
    }
    k_head<<<dim3(17, NB), 256>>>(Wreg, Wq, bq, Wq1, bq1, option, Wq2, bq2, breg, out);
}

// round 11
// speedup vs baseline: 1.6536x; 1.0027x over previous
#include <cuda_runtime.h>
#include <cuda_bf16.h>
#include <cstdint>

#define NB 32
#define NN 1024
#define NF 32
#define ND 64
#define NH 64
#define NJ (NB*ND)   /* 2048 */

// ---------------- scratch (device globals; no allocations) ----------------
__device__ __align__(16) float g_MU1[NN*NJ];            // mu_1, layout [n][b*64+d]
__device__ __align__(16) float g_MUF[NN*NJ];            // current mu state fp32
__device__ __align__(16) __nv_bfloat16 g_Abin[NN*NN];   // binarized adjacency
__device__ __align__(16) __nv_bfloat16 g_Vht[NJ*NN];    // V^T high part  [j][n]
__device__ __align__(16) __nv_bfloat16 g_Vlt[NJ*NN];    // V^T residual   [j][n]
__device__ __align__(16) float g_C3[NN*ND];             // mu3[n,d] + b2[d]

// ---------- fused: binarize adj row + C3 = mu3 + b2 (one pass over adj) ----------
__global__ __launch_bounds__(64) void k_adj(const float* __restrict__ adj,
        const float* __restrict__ W3, const float* __restrict__ b3,
        const float* __restrict__ W4, const float* __restrict__ b4,
        const float* __restrict__ b2) {
    __shared__ float adjs[NN];
    __shared__ float mu4s[ND];
    int n = blockIdx.x, tid = threadIdx.x;
    #pragma unroll
    for (int i = 0; i < 4; ++i) {
        int q = tid + i*64;
        *(float4*)&adjs[q*4] = *(const float4*)&adj[(size_t)n*NN + q*4];
    }
    __syncthreads();
    // binarize this row -> g_Abin (uint4 = 8 bf16 per write)
    const __nv_bfloat16 one = __float2bfloat16(1.f);
    const __nv_bfloat16 zero = __float2bfloat16(0.f);
    #pragma unroll
    for (int i = 0; i < 2; ++i) {
        int idx = tid + i*64;                // 128 uint4 total
        int base = idx * 8;
        union { uint4 u; __nv_bfloat16 h[8]; } w;
        #pragma unroll
        for (int e = 0; e < 8; ++e) w.h[e] = (adjs[base + e] > 0.f) ? one : zero;
        *(uint4*)&g_Abin[(size_t)n*NN + base] = w.u;
    }
    // mu4 = sum_m relu(adj[n][m]*W4 + b4)
    float w4 = W4[tid], bb4 = b4[tid];
    float acc = 0.f;
    #pragma unroll 8
    for (int m = 0; m < NN; ++m) acc += fmaxf(fmaf(adjs[m], w4, bb4), 0.f);
    mu4s[tid] = acc;
    __syncthreads();
    float a2 = b3[tid] + b2[tid];
    #pragma unroll 8
    for (int dp = 0; dp < ND; ++dp) a2 = fmaf(mu4s[dp], W3[tid*ND + dp], a2);
    g_C3[n*ND + tid] = a2;
}

// ---------------- mu_1 = relu(xv @ mu1), also init state ----------------
__global__ __launch_bounds__(256) void k_mu1(const float* __restrict__ xv,
                                             const float* __restrict__ mu1w) {
    __shared__ float xs[128][NF];
    int mt = blockIdx.x, b = blockIdx.y;
    int n0 = mt * 128, tid = threadIdx.x;
    #pragma unroll
    for (int i = 0; i < 4; ++i) {
        int q = tid + i*256;                  // 1024 float4 total
        int r = q >> 3, f4 = (q & 7) * 4;
        *(float4*)&xs[r][f4] = *(const float4*)&xv[(size_t)(b*NN + n0 + r)*NF + f4];
    }
    __syncthreads();
    int d = tid & 63, rq = tid >> 6;
    float w[NF];
    #pragma unroll
    for (int f = 0; f < NF; ++f) w[f] = mu1w[f*ND + d];
    for (int i = 0; i < 32; ++i) {
        int r = rq*32 + i;
        float acc = 0.f;
        #pragma unroll
        for (int f = 0; f < NF; ++f) acc = fmaf(xs[r][f], w[f], acc);
        acc = fmaxf(acc, 0.f);
        int o = (n0 + r)*NJ + b*ND + d;
        g_MU1[o] = acc;
        g_MUF[o] = acc;                       // t = 0 state
    }
}

// ------- V = MUF @ W2^T (fp32), written TRANSPOSED split-bf16: g_Vt[j][n] -------
__global__ __launch_bounds__(256) void k_proj(const float* __restrict__ W2) {
    __shared__ __align__(16) char sbuf[2*64*65*4];      // 33.3 KB, reused
    float (*mus)[65] = (float(*)[65])sbuf;
    float (*w2s)[65] = (float(*)[65])(sbuf + 64*65*sizeof(float));
    int mt = blockIdx.x, b = blockIdx.y;
    int m0 = mt * 64, tid = threadIdx.x;
    #pragma unroll
    for (int i = 0; i < 4; ++i) {
        int q = tid + i*256;                  // 1024 float4 each
        int r = q >> 4, dq = (q & 15) * 4;
        float4 v = *(const float4*)&g_MUF[(size_t)(m0 + r)*NJ + b*ND + dq];
        mus[r][dq] = v.x; mus[r][dq+1] = v.y; mus[r][dq+2] = v.z; mus[r][dq+3] = v.w;
        float4 w = *(const float4*)&W2[r*ND + dq];
        w2s[r][dq] = w.x; w2s[r][dq+1] = w.y; w2s[r][dq+2] = w.z; w2s[r][dq+3] = w.w;
    }
    __syncthreads();
    int tx = tid & 15, ty = tid >> 4;
    float acc[4][4] = {};
    for (int dp = 0; dp < ND; ++dp) {
        float mv[4], wv[4];
        #pragma unroll
        for (int j = 0; j < 4; ++j) mv[j] = mus[ty + 16*j][dp];
        #pragma unroll
        for (int j = 0; j < 4; ++j) wv[j] = w2s[tx + 16*j][dp];
        #pragma unroll
        for (int ii = 0; ii < 4; ++ii)
            #pragma unroll
            for (int jj = 0; jj < 4; ++jj) acc[ii][jj] = fmaf(mv[ii], wv[jj], acc[ii][jj]);
    }
    __syncthreads();                          // done with mus/w2s; reuse sbuf
    __nv_bfloat16 (*vhi)[72] = (__nv_bfloat16(*)[72])sbuf;
    __nv_bfloat16 (*vlo)[72] = (__nv_bfloat16(*)[72])(sbuf + 64*72*sizeof(__nv_bfloat16));
    #pragma unroll
    for (int ii = 0; ii < 4; ++ii)
        #pragma unroll
        for (int jj = 0; jj < 4; ++jj) {
            int r = ty + 16*ii, d = tx + 16*jj;
            float v = acc[ii][jj];
            __nv_bfloat16 hi = __float2bfloat16(v);
            vhi[d][r] = hi;
            vlo[d][r] = __float2bfloat16(v - __bfloat162float(hi));
        }
    __syncthreads();
    #pragma unroll
    for (int i = 0; i < 2; ++i) {
        int idx = tid + i*256;                // 512 uint4 per buffer
        int jd = idx >> 3, q = idx & 7;
        size_t go = (size_t)(b*ND + jd)*NN + m0 + q*8;
        *(uint4*)&g_Vht[go] = *(uint4*)&vhi[jd][q*8];
        *(uint4*)&g_Vlt[go] = *(uint4*)&vlo[jd][q*8];
    }
}

// ------- big GEMM: MUF_new = relu(A @ (Vhi + Vlo) + MU1 + C3), split-bf16 -------
// BM=128 x BJ=64 tiles, grid 256 blocks, 2 CTAs/SM for latency hiding.
#define BM 128
#define BJ 64
#define BK 32
#define PITCH 40
#define KT (NN / BK)

__global__ __launch_bounds__(256, 2) void k_gemm() {
    __shared__ __align__(16) __nv_bfloat16 As[BM*PITCH];   // [m][k] 10.2 KB
    __shared__ __align__(16) __nv_bfloat16 Bh[BJ*PITCH];   // [j][k] V_hi 5.1 KB
    __shared__ __align__(16) __nv_bfloat16 Bl[BJ*PITCH];   // [j][k] V_lo 5.1 KB
    int jt = blockIdx.x, mt = blockIdx.y;    // jt 0..31, mt 0..7
    int m0 = mt * BM, j0 = jt * BJ;
    int tid = threadIdx.x, lane = tid & 31, warp = tid >> 5;
    int wm = warp >> 1, wj = warp & 1;       // 4 x 2 warps, warp tile 32m x 32j
    int g = lane >> 2, t = lane & 3;

    float acc[2][4][4];
    #pragma unroll
    for (int a = 0; a < 2; ++a)
        #pragma unroll
        for (int c = 0; c < 4; ++c)
            #pragma unroll
            for (int e = 0; e < 4; ++e) acc[a][c][e] = 0.f;

    // prologue: tile 0 -> smem (A: 512 uint4 = 2/thread; Bh,Bl: 256 uint4 = 1/thread)
    {
        #pragma unroll
        for (int i = 0; i < 2; ++i) {
            int idx = tid + i*256;
            int row = idx >> 2, kq = idx & 3;
            *(uint4*)&As[row*PITCH + kq*8] =
                *(const uint4*)&g_Abin[(size_t)(m0 + row)*NN + kq*8];
        }
        int brow = tid >> 2, bkq = tid & 3;
        *(uint4*)&Bh[brow*PITCH + bkq*8] =
            *(const uint4*)&g_Vht[(size_t)(j0 + brow)*NN + bkq*8];
        *(uint4*)&Bl[brow*PITCH + bkq*8] =
            *(const uint4*)&g_Vlt[(size_t)(j0 + brow)*NN + bkq*8];
    }
    __syncthreads();

    for (int kt = 0; kt < KT; ++kt) {
        uint4 pa[2], pbh, pbl;
        bool next = (kt + 1 < KT);
        int brow = tid >> 2, bkq = tid & 3;
        if (next) {
            int k0 = (kt + 1) * BK;
            #pragma unroll
            for (int i = 0; i < 2; ++i) {
                int idx = tid + i*256;
                int row = idx >> 2, kq = idx & 3;
                pa[i] = *(const uint4*)&g_Abin[(size_t)(m0 + row)*NN + k0 + kq*8];
            }
            pbh = *(const uint4*)&g_Vht[(size_t)(j0 + brow)*NN + k0 + bkq*8];
            pbl = *(const uint4*)&g_Vlt[(size_t)(j0 + brow)*NN + k0 + bkq*8];
        }
        // compute on current smem tile
        #pragma unroll
        for (int ks = 0; ks < 2; ++ks) {
            int koff = ks * 16;
            uint32_t af[2][4], bfh[4][2], bfl[4][2];
            #pragma unroll
            for (int mf = 0; mf < 2; ++mf) {
                int rb = wm*32 + mf*16;
                af[mf][0] = *(const uint32_t*)&As[(rb+g  )*PITCH + koff + 2*t];
                af[mf][1] = *(const uint32_t*)&As[(rb+g+8)*PITCH + koff + 2*t];
                af[mf][2] = *(const uint32_t*)&As[(rb+g  )*PITCH + koff + 2*t + 8];
                af[mf][3] = *(const uint32_t*)&As[(rb+g+8)*PITCH + koff + 2*t + 8];
            }
            #pragma unroll
            for (int jf = 0; jf < 4; ++jf) {
                int jb = wj*32 + jf*8 + g;
                bfh[jf][0] = *(const uint32_t*)&Bh[jb*PITCH + koff + 2*t];
                bfh[jf][1] = *(const uint32_t*)&Bh[jb*PITCH + koff + 2*t + 8];
                bfl[jf][0] = *(const uint32_t*)&Bl[jb*PITCH + koff + 2*t];
                bfl[jf][1] = *(const uint32_t*)&Bl[jb*PITCH + koff + 2*t + 8];
            }
            #pragma unroll
            for (int mf = 0; mf < 2; ++mf)
                #pragma unroll
                for (int jf = 0; jf < 4; ++jf) {
                    asm volatile(
                        "mma.sync.aligned.m16n8k16.row.col.f32.bf16.bf16.f32 "
                        "{%0,%1,%2,%3}, {%4,%5,%6,%7}, {%8,%9}, {%0,%1,%2,%3};\n"
                        : "+f"(acc[mf][jf][0]), "+f"(acc[mf][jf][1]),
                          "+f"(acc[mf][jf][2]), "+f"(acc[mf][jf][3])
                        : "r"(af[mf][0]), "r"(af[mf][1]), "r"(af[mf][2]), "r"(af[mf][3]),
                          "r"(bfh[jf][0]), "r"(bfh[jf][1]));
                    asm volatile(
                        "mma.sync.aligned.m16n8k16.row.col.f32.bf16.bf16.f32 "
                        "{%0,%1,%2,%3}, {%4,%5,%6,%7}, {%8,%9}, {%0,%1,%2,%3};\n"
                        : "+f"(acc[mf][jf][0]), "+f"(acc[mf][jf][1]),
                          "+f"(acc[mf][jf][2]), "+f"(acc[mf][jf][3])
                        : "r"(af[mf][0]), "r"(af[mf][1]), "r"(af[mf][2]), "r"(af[mf][3]),
                          "r"(bfl[jf][0]), "r"(bfl[jf][1]));
                }
        }
        __syncthreads();          // done reading current tile
        if (next) {
            #pragma unroll
            for (int i = 0; i < 2; ++i) {
                int idx = tid + i*256;
                int row = idx >> 2, kq = idx & 3;
                *(uint4*)&As[row*PITCH + kq*8] = pa[i];
            }
            *(uint4*)&Bh[brow*PITCH + bkq*8] = pbh;
            *(uint4*)&Bl[brow*PITCH + bkq*8] = pbl;
        }
        __syncthreads();          // next tile visible to all warps
    }

    // epilogue: relu(acc + MU1 + C3) -> MUF
    #pragma unroll
    for (int mf = 0; mf < 2; ++mf)
        #pragma unroll
        for (int jf = 0; jf < 4; ++jf) {
            int n0r = m0 + wm*32 + mf*16 + g;
            int jc = j0 + wj*32 + jf*8 + 2*t;
            int dd = jc & 63;
            float2 m1 = *(const float2*)&g_MU1[(size_t)n0r*NJ + jc];
            float2 c3 = *(const float2*)&g_C3[n0r*ND + dd];
            float2 o0;
            o0.x = fmaxf(acc[mf][jf][0] + m1.x + c3.x, 0.f);
            o0.y = fmaxf(acc[mf][jf][1] + m1.y + c3.y, 0.f);
            *(float2*)&g_MUF[(size_t)n0r*NJ + jc] = o0;
            float2 m1b = *(const float2*)&g_MU1[(size_t)(n0r+8)*NJ + jc];
            float2 c3b = *(const float2*)&g_C3[(n0r+8)*ND + dd];
            float2 o1;
            o1.x = fmaxf(acc[mf][jf][2] + m1b.x + c3b.x, 0.f);
            o1.y = fmaxf(acc[mf][jf][3] + m1b.y + c3b.y, 0.f);
            *(float2*)&g_MUF[(size_t)(n0r+8)*NJ + jc] = o1;
        }
}

// ---- head (fused mean + option-branch): out = relu(q_@Wreg^T+breg)@Wq^T+bq ----
__global__ __launch_bounds__(256) void k_head(const float* __restrict__ Wreg,
        const float* __restrict__ Wq, const float* __restrict__ bq,
        const float* __restrict__ Wq1, const float* __restrict__ bq1,
        const float* __restrict__ option, const float* __restrict__ Wq2,
        const float* __restrict__ bq2, const float* __restrict__ breg,
        float* __restrict__ out) {
    __shared__ float xs[64][ND];
    __shared__ float Ws[NH][ND + 1];
    __shared__ float wqs[NH];
    __shared__ float t2s[NH];
    __shared__ float red[4][ND];
    __shared__ float means[ND];
    int rt = blockIdx.x, b = blockIdx.y;
    int r0 = rt * 64, tid = threadIdx.x, lane = tid & 31, warp = tid >> 5;
    // stage Wreg first half (mu part)
    #pragma unroll
    for (int i = 0; i < 4; ++i) {
        int q = tid + i*256;                  // 1024 float4
        int h = q >> 4, dq = (q & 15) * 4;
        float4 w = *(const float4*)&Wreg[h*(2*ND) + dq];
        Ws[h][dq] = w.x; Ws[h][dq+1] = w.y; Ws[h][dq+2] = w.z; Ws[h][dq+3] = w.w;
    }
    if (tid < NH) wqs[tid] = Wq[tid];
    // option branch: t2s[h] = breg[h] + sum_d (opt*Wq2[d]+bq2[d]) * Wreg[h][64+d]
    if (tid < NH) {
        float opt = option[b];
        float acc = breg[tid];
        #pragma unroll 8
        for (int d = 0; d < ND; ++d)
            acc = fmaf(fmaf(opt, Wq2[d], bq2[d]), Wreg[tid*(2*ND) + ND + d], acc);
        t2s[tid] = acc;
    }
    if (rt < 16) {
        // regular node rows
        #pragma unroll
        for (int i = 0; i < 4; ++i) {
            int q = tid + i*256;
            int r = q >> 4, dq = (q & 15) * 4;
            *(float4*)&xs[r][dq] = *(const float4*)&g_MUF[(size_t)(r0 + r)*NJ + b*ND + dq];
        }
    } else {
        // mean row: reduce MUF over nodes, project thru Wq1
        int d = tid & 63, no = tid >> 6;
        float s = 0.f;
        #pragma unroll 4
        for (int n = no; n < NN; n += 4) s += g_MUF[(size_t)n*NJ + b*ND + d];
        red[no][d] = s;
        __syncthreads();
        if (tid < ND)
            means[tid] = (red[0][tid] + red[1][tid] + red[2][tid] + red[3][tid]) * (1.0f/NN);
        __syncthreads();
        if (tid < ND) {
            float acc = bq1[tid];
            #pragma unroll 8
            for (int dp = 0; dp < ND; ++dp) acc = fmaf(means[dp], Wq1[tid*ND + dp], acc);
            xs[0][tid] = fmaxf(acc, 0.f);
        }
        // rows 1..63 unused (stores guarded below)
    }
    __syncthreads();
    float g0i = t2s[lane], g1i = t2s[lane + 32];
    float wq0 = wqs[lane], wq1 = wqs[lane + 32];
    for (int jj = 0; jj < 8; ++jj) {
        int r = warp*8 + jj;
        int rr = r0 + r;
        float a0 = g0i, a1 = g1i;
        #pragma unroll 16
        for (int dp = 0; dp < ND; ++dp) {
            float xd = xs[r][dp];
            a0 = fmaf(xd, Ws[lane][dp], a0);
            a1 = fmaf(xd, Ws[lane + 32][dp], a1);
        }
        float v = fmaxf(a0, 0.f)*wq0 + fmaxf(a1, 0.f)*wq1;
        #pragma unroll
        for (int o = 16; o; o >>= 1) v += __shfl_xor_sync(0xffffffffu, v, o);
        if (lane == 0 && rr <= NN) out[b*(NN + 1) + rr] = v + bq[0];
    }
}

// ---------------- launch ----------------
extern "C" void kernel_launch(void* const* d_in, const int* in_sizes, int n_in,
                              void* d_out, int out_size) {
    const float* xv     = (const float*)d_in[0];
    const float* option = (const float*)d_in[1];
    const float* adj    = (const float*)d_in[2];
    const float* mu1w   = (const float*)d_in[3];
    const float* W2     = (const float*)d_in[4];
    const float* b2     = (const float*)d_in[5];
    const float* W3     = (const float*)d_in[6];
    const float* b3     = (const float*)d_in[7];
    const float* W4     = (const float*)d_in[8];
    const float* b4     = (const float*)d_in[9];
    const float* Wq1    = (const float*)d_in[10];
    const float* bq1    = (const float*)d_in[11];
    const float* Wq2    = (const float*)d_in[12];
    const float* bq2    = (const float*)d_in[13];
    const float* Wreg   = (const float*)d_in[14];
    const float* breg   = (const float*)d_in[15];
    const float* Wq     = (const float*)d_in[16];
    const float* bq     = (const float*)d_in[17];
    float* out = (float*)d_out;

    k_adj<<<NN, 64>>>(adj, W3, b3, W4, b4, b2);          // binarize + C3
    k_mu1<<<dim3(8, NB), 256>>>(xv, mu1w);
    for (int t = 1; t < 4; ++t) {
        k_proj<<<dim3(16, NB), 256>>>(W2);   // V = MUF @ W2^T (split bf16, transposed)
        k_gemm<<<dim3(32, 8), 256>>>();      // MUF = relu(A @ V + MU1 + C3)
    }
    k_head<<<dim3(17, NB), 256>>>(Wreg, Wq, bq, Wq1, bq1, option, Wq2, bq2, breg, out);
}

// round 15
// speedup vs baseline: 1.8104x; 1.0948x over previous
#include <cuda_runtime.h>
#include <cuda_bf16.h>
#include <cstdint>

#define NB 32
#define NN 1024
#define NF 32
#define ND 64
#define NH 64
#define NJ (NB*ND)   /* 2048 */

// ---------------- scratch (device globals; no allocations) ----------------
__device__ __align__(16) float g_MU1[NN*NJ];            // mu_1, layout [n][b*64+d]
__device__ __align__(16) float g_MUF[NN*NJ];            // current mu state fp32
__device__ __align__(16) __nv_bfloat16 g_Abin[NN*NN];   // binarized adjacency
__device__ __align__(16) __nv_bfloat16 g_Vht[NJ*NN];    // V^T high part  [j][n]
__device__ __align__(16) __nv_bfloat16 g_Vlt[NJ*NN];    // V^T residual   [j][n]
__device__ __align__(16) float g_C3[NN*ND];             // mu3[n,d] + b2[d]

__device__ __forceinline__ uint32_t smem_u32(const void* p) {
    uint32_t a;
    asm("{ .reg .u64 t; cvta.to.shared.u64 t, %1; cvt.u32.u64 %0, t; }" : "=r"(a) : "l"(p));
    return a;
}

// ---------- fused: binarize adj row + C3 = mu3 + b2 (one pass over adj) ----------
__global__ __launch_bounds__(64) void k_adj(const float* __restrict__ adj,
        const float* __restrict__ W3, const float* __restrict__ b3,
        const float* __restrict__ W4, const float* __restrict__ b4,
        const float* __restrict__ b2) {
    __shared__ float adjs[NN];
    __shared__ float mu4s[ND];
    int n = blockIdx.x, tid = threadIdx.x;
    #pragma unroll
    for (int i = 0; i < 4; ++i) {
        int q = tid + i*64;
        *(float4*)&adjs[q*4] = *(const float4*)&adj[(size_t)n*NN + q*4];
    }
    __syncthreads();
    const __nv_bfloat16 one = __float2bfloat16(1.f);
    const __nv_bfloat16 zero = __float2bfloat16(0.f);
    #pragma unroll
    for (int i = 0; i < 2; ++i) {
        int idx = tid + i*64;
        int base = idx * 8;
        union { uint4 u; __nv_bfloat16 h[8]; } w;
        #pragma unroll
        for (int e = 0; e < 8; ++e) w.h[e] = (adjs[base + e] > 0.f) ? one : zero;
        *(uint4*)&g_Abin[(size_t)n*NN + base] = w.u;
    }
    float w4 = W4[tid], bb4 = b4[tid];
    float acc = 0.f;
    #pragma unroll 8
    for (int m = 0; m < NN; ++m) acc += fmaxf(fmaf(adjs[m], w4, bb4), 0.f);
    mu4s[tid] = acc;
    __syncthreads();
    float a2 = b3[tid] + b2[tid];
    #pragma unroll 8
    for (int dp = 0; dp < ND; ++dp) a2 = fmaf(mu4s[dp], W3[tid*ND + dp], a2);
    g_C3[n*ND + tid] = a2;
}

// ---------------- mu_1 = relu(xv @ mu1), also init state ----------------
__global__ __launch_bounds__(256) void k_mu1(const float* __restrict__ xv,
                                             const float* __restrict__ mu1w) {
    __shared__ float xs[128][NF];
    int mt = blockIdx.x, b = blockIdx.y;
    int n0 = mt * 128, tid = threadIdx.x;
    #pragma unroll
    for (int i = 0; i < 4; ++i) {
        int q = tid + i*256;
        int r = q >> 3, f4 = (q & 7) * 4;
        *(float4*)&xs[r][f4] = *(const float4*)&xv[(size_t)(b*NN + n0 + r)*NF + f4];
    }
    __syncthreads();
    int d = tid & 63, rq = tid >> 6;
    float w[NF];
    #pragma unroll
    for (int f = 0; f < NF; ++f) w[f] = mu1w[f*ND + d];
    for (int i = 0; i < 32; ++i) {
        int r = rq*32 + i;
        float acc = 0.f;
        #pragma unroll
        for (int f = 0; f < NF; ++f) acc = fmaf(xs[r][f], w[f], acc);
        acc = fmaxf(acc, 0.f);
        int o = (n0 + r)*NJ + b*ND + d;
        g_MU1[o] = acc;
        g_MUF[o] = acc;
    }
}

// ------- V = MUF @ W2^T (fp32), written TRANSPOSED split-bf16: g_Vt[j][n] -------
__global__ __launch_bounds__(256) void k_proj(const float* __restrict__ W2) {
    __shared__ __align__(16) char sbuf[2*64*65*4];
    float (*mus)[65] = (float(*)[65])sbuf;
    float (*w2s)[65] = (float(*)[65])(sbuf + 64*65*sizeof(float));
    int mt = blockIdx.x, b = blockIdx.y;
    int m0 = mt * 64, tid = threadIdx.x;
    #pragma unroll
    for (int i = 0; i < 4; ++i) {
        int q = tid + i*256;
        int r = q >> 4, dq = (q & 15) * 4;
        float4 v = *(const float4*)&g_MUF[(size_t)(m0 + r)*NJ + b*ND + dq];
        mus[r][dq] = v.x; mus[r][dq+1] = v.y; mus[r][dq+2] = v.z; mus[r][dq+3] = v.w;
        float4 w = *(const float4*)&W2[r*ND + dq];
        w2s[r][dq] = w.x; w2s[r][dq+1] = w.y; w2s[r][dq+2] = w.z; w2s[r][dq+3] = w.w;
    }
    __syncthreads();
    int tx = tid & 15, ty = tid >> 4;
    float acc[4][4] = {};
    for (int dp = 0; dp < ND; ++dp) {
        float mv[4], wv[4];
        #pragma unroll
        for (int j = 0; j < 4; ++j) mv[j] = mus[ty + 16*j][dp];
        #pragma unroll
        for (int j = 0; j < 4; ++j) wv[j] = w2s[tx + 16*j][dp];
        #pragma unroll
        for (int ii = 0; ii < 4; ++ii)
            #pragma unroll
            for (int jj = 0; jj < 4; ++jj) acc[ii][jj] = fmaf(mv[ii], wv[jj], acc[ii][jj]);
    }
    __syncthreads();
    __nv_bfloat16 (*vhi)[72] = (__nv_bfloat16(*)[72])sbuf;
    __nv_bfloat16 (*vlo)[72] = (__nv_bfloat16(*)[72])(sbuf + 64*72*sizeof(__nv_bfloat16));
    #pragma unroll
    for (int ii = 0; ii < 4; ++ii)
        #pragma unroll
        for (int jj = 0; jj < 4; ++jj) {
            int r = ty + 16*ii, d = tx + 16*jj;
            float v = acc[ii][jj];
            __nv_bfloat16 hi = __float2bfloat16(v);
            vhi[d][r] = hi;
            vlo[d][r] = __float2bfloat16(v - __bfloat162float(hi));
        }
    __syncthreads();
    #pragma unroll
    for (int i = 0; i < 2; ++i) {
        int idx = tid + i*256;
        int jd = idx >> 3, q = idx & 7;
        size_t go = (size_t)(b*ND + jd)*NN + m0 + q*8;
        *(uint4*)&g_Vht[go] = *(uint4*)&vhi[jd][q*8];
        *(uint4*)&g_Vlt[go] = *(uint4*)&vlo[jd][q*8];
    }
}

// ------- big GEMM: MUF_new = relu(A @ (Vhi + Vlo) + MU1 + C3), split-bf16 -------
// HMMA + cp.async 3-stage pipeline, 1 barrier per k-tile. BM=128 x BJ=64,
// grid 256 blocks, 2 CTAs/SM.
#define BM 128
#define BJ 64
#define BK 32
#define PITCH 40
#define KT (NN / BK)
#define STAGES 3
#define A_BYTES (BM*PITCH*2)                 /* 10240 */
#define B_BYTES (BJ*PITCH*2)                 /*  5120 */
#define STAGE_BYTES (A_BYTES + 2*B_BYTES)    /* 20480 */
#define GDYN (STAGES*STAGE_BYTES)            /* 61440 */

__global__ __launch_bounds__(256, 2) void k_gemm() {
    extern __shared__ __align__(16) char dsm[];
    int jt = blockIdx.x, mt = blockIdx.y;    // jt 0..31, mt 0..7
    int m0 = mt * BM, j0 = jt * BJ;
    int tid = threadIdx.x, lane = tid & 31, warp = tid >> 5;
    int wm = warp >> 1, wj = warp & 1;       // 4 x 2 warps, warp tile 32m x 32j
    int g = lane >> 2, t = lane & 3;
    uint32_t sbase = smem_u32(dsm);

    // issue one stage's copies (4 x 16B cp.async per thread)
    auto issue_stage = [&](int chunk, int p) {
        int k0 = chunk * BK;
        uint32_t st = sbase + p*STAGE_BYTES;
        #pragma unroll
        for (int i = 0; i < 2; ++i) {
            int idx = tid + i*256;
            int row = idx >> 2, kq = idx & 3;
            uint32_t dst = st + (uint32_t)(row*PITCH + kq*8)*2;
            const void* src = &g_Abin[(size_t)(m0 + row)*NN + k0 + kq*8];
            asm volatile("cp.async.cg.shared.global [%0], [%1], 16;"
                         :: "r"(dst), "l"(src) : "memory");
        }
        int brow = tid >> 2, bkq = tid & 3;
        uint32_t bo = (uint32_t)(brow*PITCH + bkq*8)*2;
        const void* srch = &g_Vht[(size_t)(j0 + brow)*NN + k0 + bkq*8];
        const void* srcl = &g_Vlt[(size_t)(j0 + brow)*NN + k0 + bkq*8];
        asm volatile("cp.async.cg.shared.global [%0], [%1], 16;"
                     :: "r"(st + A_BYTES + bo), "l"(srch) : "memory");
        asm volatile("cp.async.cg.shared.global [%0], [%1], 16;"
                     :: "r"(st + A_BYTES + B_BYTES + bo), "l"(srcl) : "memory");
        asm volatile("cp.async.commit_group;" ::: "memory");
    };

    float acc[2][4][4];
    #pragma unroll
    for (int a = 0; a < 2; ++a)
        #pragma unroll
        for (int c = 0; c < 4; ++c)
            #pragma unroll
            for (int e = 0; e < 4; ++e) acc[a][c][e] = 0.f;

    issue_stage(0, 0);
    issue_stage(1, 1);

    for (int kt = 0; kt < KT; ++kt) {
        if (kt < KT - 1) asm volatile("cp.async.wait_group 1;" ::: "memory");
        else             asm volatile("cp.async.wait_group 0;" ::: "memory");
        __syncthreads();          // tile kt visible to all; prior tile fully consumed

        int p = kt % STAGES;
        const __nv_bfloat16* As = (const __nv_bfloat16*)(dsm + p*STAGE_BYTES);
        const __nv_bfloat16* Bh = (const __nv_bfloat16*)(dsm + p*STAGE_BYTES + A_BYTES);
        const __nv_bfloat16* Bl = (const __nv_bfloat16*)(dsm + p*STAGE_BYTES + A_BYTES + B_BYTES);

        #pragma unroll
        for (int ks = 0; ks < 2; ++ks) {
            int koff = ks * 16;
            uint32_t af[2][4], bfh[4][2], bfl[4][2];
            #pragma unroll
            for (int mf = 0; mf < 2; ++mf) {
                int rb = wm*32 + mf*16;
                af[mf][0] = *(const uint32_t*)&As[(rb+g  )*PITCH + koff + 2*t];
                af[mf][1] = *(const uint32_t*)&As[(rb+g+8)*PITCH + koff + 2*t];
                af[mf][2] = *(const uint32_t*)&As[(rb+g  )*PITCH + koff + 2*t + 8];
                af[mf][3] = *(const uint32_t*)&As[(rb+g+8)*PITCH + koff + 2*t + 8];
            }
            #pragma unroll
            for (int jf = 0; jf < 4; ++jf) {
                int jb = wj*32 + jf*8 + g;
                bfh[jf][0] = *(const uint32_t*)&Bh[jb*PITCH + koff + 2*t];
                bfh[jf][1] = *(const uint32_t*)&Bh[jb*PITCH + koff + 2*t + 8];
                bfl[jf][0] = *(const uint32_t*)&Bl[jb*PITCH + koff + 2*t];
                bfl[jf][1] = *(const uint32_t*)&Bl[jb*PITCH + koff + 2*t + 8];
            }
            #pragma unroll
            for (int mf = 0; mf < 2; ++mf)
                #pragma unroll
                for (int jf = 0; jf < 4; ++jf) {
                    asm volatile(
                        "mma.sync.aligned.m16n8k16.row.col.f32.bf16.bf16.f32 "
                        "{%0,%1,%2,%3}, {%4,%5,%6,%7}, {%8,%9}, {%0,%1,%2,%3};\n"
                        : "+f"(acc[mf][jf][0]), "+f"(acc[mf][jf][1]),
                          "+f"(acc[mf][jf][2]), "+f"(acc[mf][jf][3])
                        : "r"(af[mf][0]), "r"(af[mf][1]), "r"(af[mf][2]), "r"(af[mf][3]),
                          "r"(bfh[jf][0]), "r"(bfh[jf][1]));
                    asm volatile(
                        "mma.sync.aligned.m16n8k16.row.col.f32.bf16.bf16.f32 "
                        "{%0,%1,%2,%3}, {%4,%5,%6,%7}, {%8,%9}, {%0,%1,%2,%3};\n"
                        : "+f"(acc[mf][jf][0]), "+f"(acc[mf][jf][1]),
                          "+f"(acc[mf][jf][2]), "+f"(acc[mf][jf][3])
                        : "r"(af[mf][0]), "r"(af[mf][1]), "r"(af[mf][2]), "r"(af[mf][3]),
                          "r"(bfl[jf][0]), "r"(bfl[jf][1]));
                }
        }
        // prefetch tile kt+2 into the buffer retired at the top-of-loop barrier
        if (kt + 2 < KT) issue_stage(kt + 2, (kt + 2) % STAGES);
    }

    // epilogue: relu(acc + MU1 + C3) -> MUF
    #pragma unroll
    for (int mf = 0; mf < 2; ++mf)
        #pragma unroll
        for (int jf = 0; jf < 4; ++jf) {
            int n0r = m0 + wm*32 + mf*16 + g;
            int jc = j0 + wj*32 + jf*8 + 2*t;
            int dd = jc & 63;
            float2 m1 = *(const float2*)&g_MU1[(size_t)n0r*NJ + jc];
            float2 c3 = *(const float2*)&g_C3[n0r*ND + dd];
            float2 o0;
            o0.x = fmaxf(acc[mf][jf][0] + m1.x + c3.x, 0.f);
            o0.y = fmaxf(acc[mf][jf][1] + m1.y + c3.y, 0.f);
            *(float2*)&g_MUF[(size_t)n0r*NJ + jc] = o0;
            float2 m1b = *(const float2*)&g_MU1[(size_t)(n0r+8)*NJ + jc];
            float2 c3b = *(const float2*)&g_C3[(n0r+8)*ND + dd];
            float2 o1;
            o1.x = fmaxf(acc[mf][jf][2] + m1b.x + c3b.x, 0.f);
            o1.y = fmaxf(acc[mf][jf][3] + m1b.y + c3b.y, 0.f);
            *(float2*)&g_MUF[(size_t)(n0r+8)*NJ + jc] = o1;
        }
}

// ---- head (fused mean + option-branch): out = relu(q_@Wreg^T+breg)@Wq^T+bq ----
__global__ __launch_bounds__(256) void k_head(const float* __restrict__ Wreg,
        const float* __restrict__ Wq, const float* __restrict__ bq,
        const float* __restrict__ Wq1, const float* __restrict__ bq1,
        const float* __restrict__ option, const float* __restrict__ Wq2,
        const float* __restrict__ bq2, const float* __restrict__ breg,
        float* __restrict__ out) {
    __shared__ float xs[64][ND];
    __shared__ float Ws[NH][ND + 1];
    __shared__ float wqs[NH];
    __shared__ float t2s[NH];
    __shared__ float red[4][ND];
    __shared__ float means[ND];
    int rt = blockIdx.x, b = blockIdx.y;
    int r0 = rt * 64, tid = threadIdx.x, lane = tid & 31, warp = tid >> 5;
    #pragma unroll
    for (int i = 0; i < 4; ++i) {
        int q = tid + i*256;
        int h = q >> 4, dq = (q & 15) * 4;
        float4 w = *(const float4*)&Wreg[h*(2*ND) + dq];
        Ws[h][dq] = w.x; Ws[h][dq+1] = w.y; Ws[h][dq+2] = w.z; Ws[h][dq+3] = w.w;
    }
    if (tid < NH) wqs[tid] = Wq[tid];
    if (tid < NH) {
        float opt = option[b];
        float acc = breg[tid];
        #pragma unroll 8
        for (int d = 0; d < ND; ++d)
            acc = fmaf(fmaf(opt, Wq2[d], bq2[d]), Wreg[tid*(2*ND) + ND + d], acc);
        t2s[tid] = acc;
    }
    if (rt < 16) {
        #pragma unroll
        for (int i = 0; i < 4; ++i) {
            int q = tid + i*256;
            int r = q >> 4, dq = (q & 15) * 4;
            *(float4*)&xs[r][dq] = *(const float4*)&g_MUF[(size_t)(r0 + r)*NJ + b*ND + dq];
        }
    } else {
        int d = tid & 63, no = tid >> 6;
        float s = 0.f;
        #pragma unroll 4
        for (int n = no; n < NN; n += 4) s += g_MUF[(size_t)n*NJ + b*ND + d];
        red[no][d] = s;
        __syncthreads();
        if (tid < ND)
            means[tid] = (red[0][tid] + red[1][tid] + red[2][tid] + red[3][tid]) * (1.0f/NN);
        __syncthreads();
        if (tid < ND) {
            float acc = bq1[tid];
            #pragma unroll 8
            for (int dp = 0; dp < ND; ++dp) acc = fmaf(means[dp], Wq1[tid*ND + dp], acc);
            xs[0][tid] = fmaxf(acc, 0.f);
        }
    }
    __syncthreads();
    float g0i = t2s[lane], g1i = t2s[lane + 32];
    float wq0 = wqs[lane], wq1 = wqs[lane + 32];
    for (int jj = 0; jj < 8; ++jj) {
        int r = warp*8 + jj;
        int rr = r0 + r;
        float a0 = g0i, a1 = g1i;
        #pragma unroll 16
        for (int dp = 0; dp < ND; ++dp) {
            float xd = xs[r][dp];
            a0 = fmaf(xd, Ws[lane][dp], a0);
            a1 = fmaf(xd, Ws[lane + 32][dp], a1);
        }
        float v = fmaxf(a0, 0.f)*wq0 + fmaxf(a1, 0.f)*wq1;
        #pragma unroll
        for (int o = 16; o; o >>= 1) v += __shfl_xor_sync(0xffffffffu, v, o);
        if (lane == 0 && rr <= NN) out[b*(NN + 1) + rr] = v + bq[0];
    }
}

// ---------------- launch ----------------
extern "C" void kernel_launch(void* const* d_in, const int* in_sizes, int n_in,
                              void* d_out, int out_size) {
    const float* xv     = (const float*)d_in[0];
    const float* option = (const float*)d_in[1];
    const float* adj    = (const float*)d_in[2];
    const float* mu1w   = (const float*)d_in[3];
    const float* W2     = (const float*)d_in[4];
    const float* b2     = (const float*)d_in[5];
    const float* W3     = (const float*)d_in[6];
    const float* b3     = (const float*)d_in[7];
    const float* W4     = (const float*)d_in[8];
    const float* b4     = (const float*)d_in[9];
    const float* Wq1    = (const float*)d_in[10];
    const float* bq1    = (const float*)d_in[11];
    const float* Wq2    = (const float*)d_in[12];
    const float* bq2    = (const float*)d_in[13];
    const float* Wreg   = (const float*)d_in[14];
    const float* breg   = (const float*)d_in[15];
    const float* Wq     = (const float*)d_in[16];
    const float* bq     = (const float*)d_in[17];
    float* out = (float*)d_out;

    // idempotent attribute set — not stream work, safe under graph capture
    cudaFuncSetAttribute(k_gemm, cudaFuncAttributeMaxDynamicSharedMemorySize, GDYN);

    k_adj<<<NN, 64>>>(adj, W3, b3, W4, b4, b2);          // binarize + C3
    k_mu1<<<dim3(8, NB), 256>>>(xv, mu1w);
    for (int t = 1; t < 4; ++t) {
        k_proj<<<dim3(16, NB), 256>>>(W2);               // V (split bf16, transposed)
        k_gemm<<<dim3(32, 8), 256, GDYN>>>();            // cp.async pipelined HMMA
    }
    k_head<<<dim3(17, NB), 256>>>(Wreg, Wq, bq, Wq1, bq1, option, Wq2, bq2, breg, out);
}